// round 16
// baseline (speedup 1.0000x reference)
#include <cuda_runtime.h>
#include <cuda_bf16.h>
#include <mma.h>
#include <math.h>
#include <stdint.h>

using namespace nvcuda;

// Problem constants: B=2, N=2048, C=1024, H=16, D=64
#define BATCH 2
#define SEQ   2048
#define CDIM  1024
#define HEADS 16
#define HDIM  64
#define ROWS  (BATCH*SEQ)          // 4096
#define FF    (4*CDIM)             // 4096

// ---------------- scratch (static device globals) ----------------
__device__ float g_raw[(size_t)ROWS*FF];    // raw GEMM output (fp32), max 4096x4096
__device__ float g_h2 [(size_t)ROWS*CDIM];  // post-attn residual (fp32); reused for h5
__device__ __nv_bfloat16 g_ah[(size_t)ROWS*FF];    // activation hi (A operand)
__device__ __nv_bfloat16 g_al[(size_t)ROWS*FF];    // activation lo
__device__ __nv_bfloat16 g_wth[(size_t)FF*CDIM];   // transposed weight hi
__device__ __nv_bfloat16 g_wtl[(size_t)FF*CDIM];   // transposed weight lo
__device__ __nv_bfloat16 g_qh[(size_t)ROWS*CDIM], g_ql[(size_t)ROWS*CDIM];
__device__ __nv_bfloat16 g_kh[(size_t)ROWS*CDIM], g_kl[(size_t)ROWS*CDIM];
__device__ __nv_bfloat16 g_vh[(size_t)ROWS*CDIM], g_vl[(size_t)ROWS*CDIM];
__device__ __nv_bfloat16 g_oh[(size_t)ROWS*CDIM], g_ol[(size_t)ROWS*CDIM];

// ===================== helpers =====================
__device__ __forceinline__ uint32_t smem_u32(const void* p) {
    return (uint32_t)__cvta_generic_to_shared(p);
}
__device__ __forceinline__ uint32_t packbf(float lo, float hi) {
    uint32_t r;
    asm("cvt.rn.bf16x2.f32 %0, %1, %2;" : "=r"(r) : "f"(hi), "f"(lo));
    return r;
}
__device__ __forceinline__ void mma16816(float* d, const uint32_t* a, uint32_t b0, uint32_t b1) {
    asm volatile(
        "mma.sync.aligned.m16n8k16.row.col.f32.bf16.bf16.f32 "
        "{%0,%1,%2,%3}, {%4,%5,%6,%7}, {%8,%9}, {%0,%1,%2,%3};\n"
        : "+f"(d[0]), "+f"(d[1]), "+f"(d[2]), "+f"(d[3])
        : "r"(a[0]), "r"(a[1]), "r"(a[2]), "r"(a[3]), "r"(b0), "r"(b1));
}
__device__ __forceinline__ void ldsm_x2(uint32_t& r0, uint32_t& r1, uint32_t addr) {
    asm volatile("ldmatrix.sync.aligned.m8n8.x2.shared.b16 {%0,%1}, [%2];"
                 : "=r"(r0), "=r"(r1) : "r"(addr));
}
__device__ __forceinline__ void ldsm_x2_t(uint32_t& r0, uint32_t& r1, uint32_t addr) {
    asm volatile("ldmatrix.sync.aligned.m8n8.x2.trans.shared.b16 {%0,%1}, [%2];"
                 : "=r"(r0), "=r"(r1) : "r"(addr));
}
__device__ __forceinline__ void cpa16(uint32_t dst, const void* src) {
    asm volatile("cp.async.cg.shared.global [%0], [%1], 16;" :: "r"(dst), "l"(src));
}
__device__ __forceinline__ float gelu_exact(float x) {
    return x * 0.5f * (1.0f + erff(x * 0.70710678118654752f));
}
__inline__ __device__ float warp_sum(float v) {
    #pragma unroll
    for (int o = 16; o > 0; o >>= 1) v += __shfl_xor_sync(0xffffffffu, v, o);
    return v;
}

// ===================== LayerNorm (fp32 out, for final) =====================
__global__ void ln_kernel(const float* __restrict__ x, const float* __restrict__ w,
                          const float* __restrict__ b, float* __restrict__ y) {
    int row = blockIdx.x;
    int tid = threadIdx.x;
    const float4* xr = (const float4*)(x + (size_t)row * CDIM);
    float4 v = xr[tid];
    float s  = v.x + v.y + v.z + v.w;
    float ss = v.x*v.x + v.y*v.y + v.z*v.z + v.w*v.w;
    __shared__ float red_s[8], red_ss[8];
    __shared__ float s_mu, s_rstd;
    int lane = tid & 31, wid = tid >> 5;
    s = warp_sum(s); ss = warp_sum(ss);
    if (lane == 0) { red_s[wid] = s; red_ss[wid] = ss; }
    __syncthreads();
    if (tid == 0) {
        float ts = 0.f, tss = 0.f;
        #pragma unroll
        for (int i = 0; i < 8; i++) { ts += red_s[i]; tss += red_ss[i]; }
        float mu  = ts * (1.0f / CDIM);
        float var = tss * (1.0f / CDIM) - mu * mu;
        s_mu = mu; s_rstd = rsqrtf(var + 1e-5f);
    }
    __syncthreads();
    float mu = s_mu, rstd = s_rstd;
    float4 w4 = ((const float4*)w)[tid], b4 = ((const float4*)b)[tid];
    float4 o;
    o.x = (v.x - mu) * rstd * w4.x + b4.x;
    o.y = (v.y - mu) * rstd * w4.y + b4.y;
    o.z = (v.z - mu) * rstd * w4.z + b4.z;
    o.w = (v.w - mu) * rstd * w4.w + b4.w;
    ((float4*)(y + (size_t)row * CDIM))[tid] = o;
}

// ===================== LayerNorm -> split bf16 =====================
__global__ void ln_split_kernel(const float* __restrict__ x, const float* __restrict__ w,
                                const float* __restrict__ b,
                                __nv_bfloat16* __restrict__ yh, __nv_bfloat16* __restrict__ yl) {
    int row = blockIdx.x;
    int tid = threadIdx.x;
    const float4* xr = (const float4*)(x + (size_t)row * CDIM);
    float4 v = xr[tid];
    float s  = v.x + v.y + v.z + v.w;
    float ss = v.x*v.x + v.y*v.y + v.z*v.z + v.w*v.w;
    __shared__ float red_s[8], red_ss[8];
    __shared__ float s_mu, s_rstd;
    int lane = tid & 31, wid = tid >> 5;
    s = warp_sum(s); ss = warp_sum(ss);
    if (lane == 0) { red_s[wid] = s; red_ss[wid] = ss; }
    __syncthreads();
    if (tid == 0) {
        float ts = 0.f, tss = 0.f;
        #pragma unroll
        for (int i = 0; i < 8; i++) { ts += red_s[i]; tss += red_ss[i]; }
        float mu  = ts * (1.0f / CDIM);
        float var = tss * (1.0f / CDIM) - mu * mu;
        s_mu = mu; s_rstd = rsqrtf(var + 1e-5f);
    }
    __syncthreads();
    float mu = s_mu, rstd = s_rstd;
    float4 w4 = ((const float4*)w)[tid], b4 = ((const float4*)b)[tid];
    float o[4];
    o[0] = (v.x - mu) * rstd * w4.x + b4.x;
    o[1] = (v.y - mu) * rstd * w4.y + b4.y;
    o[2] = (v.z - mu) * rstd * w4.z + b4.z;
    o[3] = (v.w - mu) * rstd * w4.w + b4.w;
    size_t base = (size_t)row * CDIM + tid * 4;
    #pragma unroll
    for (int i = 0; i < 4; i += 2) {
        uint32_t hp = packbf(o[i], o[i+1]);
        __nv_bfloat162 hv = *reinterpret_cast<__nv_bfloat162*>(&hp);
        float r0 = o[i]   - __bfloat162float(hv.x);
        float r1 = o[i+1] - __bfloat162float(hv.y);
        uint32_t lp = packbf(r0, r1);
        *(uint32_t*)&yh[base + i] = hp;
        *(uint32_t*)&yl[base + i] = lp;
    }
}

// ===================== weight transpose + split: W[K,N] -> Wt[N,K] hi/lo =====================
__global__ void transpose_split_kernel(const float* __restrict__ W,
                                       __nv_bfloat16* __restrict__ Th,
                                       __nv_bfloat16* __restrict__ Tl, int K, int N) {
    __shared__ float t[32][33];
    int n0 = blockIdx.x * 32, k0 = blockIdx.y * 32;
    int tx = threadIdx.x;
    for (int i = threadIdx.y; i < 32; i += 8)
        t[i][tx] = W[(size_t)(k0 + i) * N + n0 + tx];
    __syncthreads();
    for (int i = threadIdx.y; i < 32; i += 8) {
        float x = t[tx][i];
        __nv_bfloat16 h = __float2bfloat16(x);
        __nv_bfloat16 l = __float2bfloat16(x - __bfloat162float(h));
        size_t oi = (size_t)(n0 + i) * K + k0 + tx;
        Th[oi] = h; Tl[oi] = l;
    }
}

// ===================== wmma GEMM (cp.async double-buffered, reg-diet): C = A @ Wt^T (raw fp32) =====================
#define BK    32
#define LDT   40   // padded row stride in bf16 (80B = 5x16B, 16B-aligned rows)
#define GEMM_SMEM (2*2*128*LDT*2*2)   // 2 buf x 2 hl x 128 x LDT x 2B x {A,B} = 81920

__global__ __launch_bounds__(256, 2) void gemm_wmma_kernel(
    const __nv_bfloat16* __restrict__ Ahi, const __nv_bfloat16* __restrict__ Alo,
    const __nv_bfloat16* __restrict__ Bhi, const __nv_bfloat16* __restrict__ Blo,
    float* __restrict__ C, int M, int N, int K)
{
    extern __shared__ __nv_bfloat16 dsm[];
    __nv_bfloat16* Asm = dsm;                    // [buf][hl][128][LDT]
    __nv_bfloat16* Bsm = dsm + 2*2*128*LDT;

    const int tid = threadIdx.x;
    const int wid = tid >> 5;
    const int wm = wid & 3;          // m band: rows wm*32..+31
    const int wn = wid >> 2;         // n band: cols wn*64..+63
    const size_t bm = (size_t)blockIdx.y * 128;
    const size_t bn = (size_t)blockIdx.x * 128;

    const int lr = tid >> 2;             // 0..63
    const int lc = (tid & 3) * 8;        // 0,8,16,24

    const uint32_t sA = smem_u32(Asm);
    const uint32_t sB = smem_u32(Bsm);
    const size_t s64 = (size_t)64 * K;

    auto fill = [&](int buf, int k0) {
        const __nv_bfloat16* a0 = Ahi + (bm + lr) * K + k0 + lc;
        const __nv_bfloat16* a1 = Alo + (bm + lr) * K + k0 + lc;
        const __nv_bfloat16* b0 = Bhi + (bn + lr) * K + k0 + lc;
        const __nv_bfloat16* b1 = Blo + (bn + lr) * K + k0 + lc;
        uint32_t dA0 = sA + (((buf*2+0)*128 + lr)*LDT + lc)*2;
        uint32_t dA1 = sA + (((buf*2+1)*128 + lr)*LDT + lc)*2;
        uint32_t dB0 = sB + (((buf*2+0)*128 + lr)*LDT + lc)*2;
        uint32_t dB1 = sB + (((buf*2+1)*128 + lr)*LDT + lc)*2;
        const uint32_t r64 = 64*LDT*2;
        cpa16(dA0, a0);           cpa16(dA0 + r64, a0 + s64);
        cpa16(dA1, a1);           cpa16(dA1 + r64, a1 + s64);
        cpa16(dB0, b0);           cpa16(dB0 + r64, b0 + s64);
        cpa16(dB1, b1);           cpa16(dB1 + r64, b1 + s64);
        asm volatile("cp.async.commit_group;");
    };

    wmma::fragment<wmma::accumulator, 16, 16, 16, float> acc[2][4];
    #pragma unroll
    for (int i = 0; i < 2; i++)
        #pragma unroll
        for (int j = 0; j < 4; j++)
            wmma::fill_fragment(acc[i][j], 0.0f);

    const int nch = K / BK;
    fill(0, 0);
    int buf = 0;
    for (int ch = 0; ch < nch; ch++) {
        if (ch + 1 < nch) {
            fill(buf ^ 1, (ch + 1) * BK);
            asm volatile("cp.async.wait_group 1;");
        } else {
            asm volatile("cp.async.wait_group 0;");
        }
        __syncthreads();

        const __nv_bfloat16* Ah = Asm + (buf*2+0)*128*LDT;
        const __nv_bfloat16* Al = Asm + (buf*2+1)*128*LDT;
        const __nv_bfloat16* Bh = Bsm + (buf*2+0)*128*LDT;
        const __nv_bfloat16* Bl = Bsm + (buf*2+1)*128*LDT;

        #pragma unroll
        for (int kk = 0; kk < BK; kk += 16) {
            wmma::fragment<wmma::matrix_a, 16, 16, 16, __nv_bfloat16, wmma::row_major> aH[2], aL[2];
            #pragma unroll
            for (int i = 0; i < 2; i++) {
                wmma::load_matrix_sync(aH[i], Ah + (wm*32 + i*16)*LDT + kk, LDT);
                wmma::load_matrix_sync(aL[i], Al + (wm*32 + i*16)*LDT + kk, LDT);
            }
            #pragma unroll
            for (int jh = 0; jh < 2; jh++) {
                wmma::fragment<wmma::matrix_b, 16, 16, 16, __nv_bfloat16, wmma::col_major> bH[2], bL[2];
                #pragma unroll
                for (int j = 0; j < 2; j++) {
                    int ncol = wn*64 + jh*32 + j*16;
                    wmma::load_matrix_sync(bH[j], Bh + ncol*LDT + kk, LDT);
                    wmma::load_matrix_sync(bL[j], Bl + ncol*LDT + kk, LDT);
                }
                #pragma unroll
                for (int i = 0; i < 2; i++)
                    #pragma unroll
                    for (int j = 0; j < 2; j++) {
                        wmma::mma_sync(acc[i][jh*2+j], aH[i], bH[j], acc[i][jh*2+j]);
                        wmma::mma_sync(acc[i][jh*2+j], aH[i], bL[j], acc[i][jh*2+j]);
                        wmma::mma_sync(acc[i][jh*2+j], aL[i], bH[j], acc[i][jh*2+j]);
                    }
            }
        }
        __syncthreads();
        buf ^= 1;
    }

    #pragma unroll
    for (int i = 0; i < 2; i++)
        #pragma unroll
        for (int j = 0; j < 4; j++) {
            float* dst = C + (bm + wm*32 + i*16) * N + bn + wn*64 + j*16;
            wmma::store_matrix_sync(dst, acc[i][j], N, wmma::mem_row_major);
        }
}

// ===================== epilogues =====================
template<bool GELU, bool RES>
__global__ void epi_split_kernel(const float* __restrict__ Craw, const float* __restrict__ bias,
                                 const float* __restrict__ res,
                                 __nv_bfloat16* __restrict__ oh, __nv_bfloat16* __restrict__ ol,
                                 int nmask) {
    int i = (blockIdx.x * blockDim.x + threadIdx.x) * 4;
    int col = i & nmask;
    float4 v = *(const float4*)(Craw + i);
    float4 b = *(const float4*)(bias + col);
    float o[4] = {v.x + b.x, v.y + b.y, v.z + b.z, v.w + b.w};
    if (RES) {
        float4 r = *(const float4*)(res + i);
        o[0] += r.x; o[1] += r.y; o[2] += r.z; o[3] += r.w;
    }
    if (GELU) {
        #pragma unroll
        for (int j = 0; j < 4; j++) o[j] = gelu_exact(o[j]);
    }
    #pragma unroll
    for (int j = 0; j < 4; j += 2) {
        uint32_t hp = packbf(o[j], o[j+1]);
        __nv_bfloat162 hv = *reinterpret_cast<__nv_bfloat162*>(&hp);
        float r0 = o[j]   - __bfloat162float(hv.x);
        float r1 = o[j+1] - __bfloat162float(hv.y);
        uint32_t lp = packbf(r0, r1);
        *(uint32_t*)&oh[i + j] = hp;
        *(uint32_t*)&ol[i + j] = lp;
    }
}

template<bool RES>
__global__ void epi_plain_kernel(const float* __restrict__ Craw, const float* __restrict__ bias,
                                 const float* __restrict__ res, float* __restrict__ out,
                                 int nmask) {
    int i = (blockIdx.x * blockDim.x + threadIdx.x) * 4;
    int col = i & nmask;
    float4 v = *(const float4*)(Craw + i);
    float4 b = *(const float4*)(bias + col);
    v.x += b.x; v.y += b.y; v.z += b.z; v.w += b.w;
    if (RES) {
        float4 r = *(const float4*)(res + i);
        v.x += r.x; v.y += r.y; v.z += r.z; v.w += r.w;
    }
    *(float4*)(out + i) = v;
}

// ===================== tensor-core flash attention (128 Q-rows/CTA, cp.async KV pipeline) =====================
// 256 threads (8 warps), warp w owns Q rows [128*blk + 16w, +16). KV tile 64, double-buffered.
// Halves KV HBM traffic vs 64-row CTAs and doubles smem reuse per loaded KV byte.
#define AP 72
#define ATTN_PLANE_B (64*AP*2)             // 9216 bytes per plane (64 rows x AP bf16)
#define ATTN_STAGE_B (4*ATTN_PLANE_B)      // 36864 (Kh, Kl, Vh, Vl)
#define ATTN_SMEM    (2*ATTN_STAGE_B)      // 73728, dynamic (opt-in)

__global__ __launch_bounds__(256) void attn_mma_kernel(
    const __nv_bfloat16* __restrict__ qh, const __nv_bfloat16* __restrict__ ql,
    const __nv_bfloat16* __restrict__ kh, const __nv_bfloat16* __restrict__ kl,
    const __nv_bfloat16* __restrict__ vh, const __nv_bfloat16* __restrict__ vl,
    __nv_bfloat16* __restrict__ oh, __nv_bfloat16* __restrict__ ol)
{
    extern __shared__ char asmem[];
    const uint32_t sbase = smem_u32(asmem);

    const int tid = threadIdx.x, wid = tid >> 5, lane = tid & 31;
    const int g = lane >> 2, tig = lane & 3;
    const int bh = blockIdx.y, b = bh / HEADS, h = bh % HEADS;
    const int q0 = blockIdx.x * 128;
    const int hcol = h * HDIM;
    const size_t qrow = (size_t)b * SEQ + q0 + wid * 16;

    // preload Q fragments (A operand, rows g/g+8, 4 k-steps, hi+lo)
    uint32_t aQh[4][4], aQl[4][4];
    {
        const size_t r0 = (qrow + g) * CDIM, r1 = (qrow + g + 8) * CDIM;
        #pragma unroll
        for (int kk = 0; kk < 4; kk++) {
            int c0 = hcol + kk * 16 + 2 * tig, c1 = c0 + 8;
            aQh[kk][0] = *(const uint32_t*)&qh[r0 + c0];
            aQh[kk][1] = *(const uint32_t*)&qh[r1 + c0];
            aQh[kk][2] = *(const uint32_t*)&qh[r0 + c1];
            aQh[kk][3] = *(const uint32_t*)&qh[r1 + c1];
            aQl[kk][0] = *(const uint32_t*)&ql[r0 + c0];
            aQl[kk][1] = *(const uint32_t*)&ql[r1 + c0];
            aQl[kk][2] = *(const uint32_t*)&ql[r0 + c1];
            aQl[kk][3] = *(const uint32_t*)&ql[r1 + c1];
        }
    }

    // KV tile fill via cp.async: 4 planes x 512 16B-chunks, 256 threads -> 2 chunks/plane/thread
    auto fillkv = [&](int st, int kv0) {
        uint32_t base = sbase + st * ATTN_STAGE_B;
        #pragma unroll
        for (int i = 0; i < 2; i++) {
            int idx = tid + i * 256;
            int r = idx >> 3, c8 = (idx & 7) * 8;
            size_t gsrc = ((size_t)b * SEQ + kv0 + r) * CDIM + hcol + c8;
            uint32_t doff = (uint32_t)((r * AP + c8) * 2);
            cpa16(base + 0*ATTN_PLANE_B + doff, &kh[gsrc]);
            cpa16(base + 1*ATTN_PLANE_B + doff, &kl[gsrc]);
            cpa16(base + 2*ATTN_PLANE_B + doff, &vh[gsrc]);
            cpa16(base + 3*ATTN_PLANE_B + doff, &vl[gsrc]);
        }
        asm volatile("cp.async.commit_group;");
    };

    const int rsub  = lane & 7;
    const int chalf = ((lane >> 3) & 1) * 8;
    const int rv    = lane & 15;

    float of[8][4];
    #pragma unroll
    for (int j = 0; j < 8; j++) { of[j][0]=0.f; of[j][1]=0.f; of[j][2]=0.f; of[j][3]=0.f; }
    float m0 = -1e30f, m1 = -1e30f, l0 = 0.f, l1 = 0.f;

    fillkv(0, 0);
    int buf = 0;
    for (int kv0 = 0; kv0 < SEQ; kv0 += 64) {
        if (kv0 + 64 < SEQ) {
            fillkv(buf ^ 1, kv0 + 64);
            asm volatile("cp.async.wait_group 1;");
        } else {
            asm volatile("cp.async.wait_group 0;");
        }
        __syncthreads();

        const uint32_t kshb = sbase + buf*ATTN_STAGE_B + 0*ATTN_PLANE_B;
        const uint32_t kslb = sbase + buf*ATTN_STAGE_B + 1*ATTN_PLANE_B;
        const uint32_t vshb = sbase + buf*ATTN_STAGE_B + 2*ATTN_PLANE_B;
        const uint32_t vslb = sbase + buf*ATTN_STAGE_B + 3*ATTN_PLANE_B;

        // ---- S = Q @ K^T (split bf16, 3 terms) ----
        float s[8][4];
        #pragma unroll
        for (int nt = 0; nt < 8; nt++) { s[nt][0]=0.f; s[nt][1]=0.f; s[nt][2]=0.f; s[nt][3]=0.f; }
        #pragma unroll
        for (int kk = 0; kk < 4; kk++) {
            #pragma unroll
            for (int nt = 0; nt < 8; nt++) {
                uint32_t off = (uint32_t)(((nt*8 + rsub)*AP + kk*16 + chalf) * 2);
                uint32_t bh0, bh1, bl0, bl1;
                ldsm_x2(bh0, bh1, kshb + off);
                ldsm_x2(bl0, bl1, kslb + off);
                mma16816(s[nt], aQh[kk], bh0, bh1);
                mma16816(s[nt], aQh[kk], bl0, bl1);
                mma16816(s[nt], aQl[kk], bh0, bh1);
            }
        }

        // ---- online softmax on fragments ----
        float mx0 = -1e30f, mx1 = -1e30f;
        #pragma unroll
        for (int nt = 0; nt < 8; nt++) {
            s[nt][0] *= 0.125f; s[nt][1] *= 0.125f; s[nt][2] *= 0.125f; s[nt][3] *= 0.125f;
            mx0 = fmaxf(mx0, fmaxf(s[nt][0], s[nt][1]));
            mx1 = fmaxf(mx1, fmaxf(s[nt][2], s[nt][3]));
        }
        mx0 = fmaxf(mx0, __shfl_xor_sync(0xffffffffu, mx0, 1));
        mx0 = fmaxf(mx0, __shfl_xor_sync(0xffffffffu, mx0, 2));
        mx1 = fmaxf(mx1, __shfl_xor_sync(0xffffffffu, mx1, 1));
        mx1 = fmaxf(mx1, __shfl_xor_sync(0xffffffffu, mx1, 2));
        float m0n = fmaxf(m0, mx0), m1n = fmaxf(m1, mx1);
        float f0 = __expf(m0 - m0n), f1 = __expf(m1 - m1n);
        m0 = m0n; m1 = m1n;

        float ps0 = 0.f, ps1 = 0.f;
        #pragma unroll
        for (int nt = 0; nt < 8; nt++) {
            s[nt][0] = __expf(s[nt][0] - m0); ps0 += s[nt][0];
            s[nt][1] = __expf(s[nt][1] - m0); ps0 += s[nt][1];
            s[nt][2] = __expf(s[nt][2] - m1); ps1 += s[nt][2];
            s[nt][3] = __expf(s[nt][3] - m1); ps1 += s[nt][3];
        }
        ps0 += __shfl_xor_sync(0xffffffffu, ps0, 1);
        ps0 += __shfl_xor_sync(0xffffffffu, ps0, 2);
        ps1 += __shfl_xor_sync(0xffffffffu, ps1, 1);
        ps1 += __shfl_xor_sync(0xffffffffu, ps1, 2);
        l0 = l0 * f0 + ps0;
        l1 = l1 * f1 + ps1;

        #pragma unroll
        for (int j = 0; j < 8; j++) {
            of[j][0] *= f0; of[j][1] *= f0; of[j][2] *= f1; of[j][3] *= f1;
        }

        // ---- P -> split bf16 in registers (A-frag layout) ----
        uint32_t pha[8], phb[8], pla[8], plb[8];
        #pragma unroll
        for (int nt = 0; nt < 8; nt++) {
            uint32_t hp = packbf(s[nt][0], s[nt][1]);
            __nv_bfloat162 hv = *reinterpret_cast<__nv_bfloat162*>(&hp);
            pla[nt] = packbf(s[nt][0] - __bfloat162float(hv.x),
                             s[nt][1] - __bfloat162float(hv.y));
            pha[nt] = hp;
            uint32_t hp2 = packbf(s[nt][2], s[nt][3]);
            __nv_bfloat162 hv2 = *reinterpret_cast<__nv_bfloat162*>(&hp2);
            plb[nt] = packbf(s[nt][2] - __bfloat162float(hv2.x),
                             s[nt][3] - __bfloat162float(hv2.y));
            phb[nt] = hp2;
        }

        // ---- O += P @ V (split, 3 terms), V via ldmatrix.trans ----
        #pragma unroll
        for (int kk = 0; kk < 4; kk++) {
            uint32_t aH[4] = {pha[2*kk], phb[2*kk], pha[2*kk+1], phb[2*kk+1]};
            uint32_t aL[4] = {pla[2*kk], plb[2*kk], pla[2*kk+1], plb[2*kk+1]};
            #pragma unroll
            for (int j = 0; j < 8; j++) {
                uint32_t off = (uint32_t)(((kk*16 + rv)*AP + j*8) * 2);
                uint32_t bh0, bh1, bl0, bl1;
                ldsm_x2_t(bh0, bh1, vshb + off);
                ldsm_x2_t(bl0, bl1, vslb + off);
                mma16816(of[j], aH, bh0, bh1);
                mma16816(of[j], aH, bl0, bl1);
                mma16816(of[j], aL, bh0, bh1);
            }
        }
        __syncthreads();   // all reads of buf done before next fill overwrites it
        buf ^= 1;
    }

    // ---- epilogue: O /= l, write split bf16 ----
    float inv0 = 1.0f / l0, inv1 = 1.0f / l1;
    const size_t r0 = (qrow + g) * CDIM, r1 = (qrow + g + 8) * CDIM;
    #pragma unroll
    for (int j = 0; j < 8; j++) {
        int col = hcol + j * 8 + 2 * tig;
        float v0 = of[j][0] * inv0, v1 = of[j][1] * inv0;
        float v2 = of[j][2] * inv1, v3 = of[j][3] * inv1;
        uint32_t hp0 = packbf(v0, v1);
        __nv_bfloat162 h0 = *reinterpret_cast<__nv_bfloat162*>(&hp0);
        uint32_t lp0 = packbf(v0 - __bfloat162float(h0.x), v1 - __bfloat162float(h0.y));
        uint32_t hp1 = packbf(v2, v3);
        __nv_bfloat162 h1 = *reinterpret_cast<__nv_bfloat162*>(&hp1);
        uint32_t lp1 = packbf(v2 - __bfloat162float(h1.x), v3 - __bfloat162float(h1.y));
        *(uint32_t*)&oh[r0 + col] = hp0;
        *(uint32_t*)&ol[r0 + col] = lp0;
        *(uint32_t*)&oh[r1 + col] = hp1;
        *(uint32_t*)&ol[r1 + col] = lp1;
    }
}

// ===================== host =====================
static inline void transp(const float* W, __nv_bfloat16* th, __nv_bfloat16* tl, int K, int N) {
    transpose_split_kernel<<<dim3(N / 32, K / 32), dim3(32, 8)>>>(W, th, tl, K, N);
}

extern "C" void kernel_launch(void* const* d_in, const int* in_sizes, int n_in,
                              void* d_out, int out_size)
{
    const float* x      = (const float*)d_in[0];
    const float* wq     = (const float*)d_in[1];
    const float* bq     = (const float*)d_in[2];
    const float* wk     = (const float*)d_in[3];
    const float* bk     = (const float*)d_in[4];
    const float* wv     = (const float*)d_in[5];
    const float* bv     = (const float*)d_in[6];
    const float* wo     = (const float*)d_in[7];
    const float* bo     = (const float*)d_in[8];
    const float* ln1_w  = (const float*)d_in[9];
    const float* ln1_b  = (const float*)d_in[10];
    const float* ln2_w  = (const float*)d_in[11];
    const float* ln2_b  = (const float*)d_in[12];
    const float* fc1_w  = (const float*)d_in[13];
    const float* fc1_b  = (const float*)d_in[14];
    const float* fc2_w  = (const float*)d_in[15];
    const float* fc2_b  = (const float*)d_in[16];
    const float* wout   = (const float*)d_in[17];
    const float* bout   = (const float*)d_in[18];
    const float* lnout_w= (const float*)d_in[19];
    const float* lnout_b= (const float*)d_in[20];
    float* out = (float*)d_out;

    float *raw, *h2;
    __nv_bfloat16 *ah, *al, *wth, *wtl, *q_h, *q_l, *k_h, *k_l, *v_h, *v_l, *o_h, *o_l;
    cudaGetSymbolAddress((void**)&raw, g_raw);
    cudaGetSymbolAddress((void**)&h2,  g_h2);
    cudaGetSymbolAddress((void**)&ah,  g_ah);
    cudaGetSymbolAddress((void**)&al,  g_al);
    cudaGetSymbolAddress((void**)&wth, g_wth);
    cudaGetSymbolAddress((void**)&wtl, g_wtl);
    cudaGetSymbolAddress((void**)&q_h, g_qh);  cudaGetSymbolAddress((void**)&q_l, g_ql);
    cudaGetSymbolAddress((void**)&k_h, g_kh);  cudaGetSymbolAddress((void**)&k_l, g_kl);
    cudaGetSymbolAddress((void**)&v_h, g_vh);  cudaGetSymbolAddress((void**)&v_l, g_vl);
    cudaGetSymbolAddress((void**)&o_h, g_oh);  cudaGetSymbolAddress((void**)&o_l, g_ol);

    cudaFuncSetAttribute(gemm_wmma_kernel,
                         cudaFuncAttributeMaxDynamicSharedMemorySize, GEMM_SMEM);
    cudaFuncSetAttribute(attn_mma_kernel,
                         cudaFuncAttributeMaxDynamicSharedMemorySize, ATTN_SMEM);

    dim3 blk(256);
    dim3 gc(CDIM/128, ROWS/128);   // (8, 32)
    dim3 gf(FF/128,   ROWS/128);   // (32, 32)
    const int nepi_c = ROWS*CDIM/1024;
    const int nepi_f = ROWS*FF/1024;

    // 1. LN1 -> split activation
    ln_split_kernel<<<ROWS, blk>>>(x, ln1_w, ln1_b, ah, al);
    // 2-4. QKV projections -> split bf16 q,k,v
    transp(wq, wth, wtl, CDIM, CDIM);
    gemm_wmma_kernel<<<gc, blk, GEMM_SMEM>>>(ah, al, wth, wtl, raw, ROWS, CDIM, CDIM);
    epi_split_kernel<false,false><<<nepi_c, blk>>>(raw, bq, nullptr, q_h, q_l, CDIM-1);
    transp(wk, wth, wtl, CDIM, CDIM);
    gemm_wmma_kernel<<<gc, blk, GEMM_SMEM>>>(ah, al, wth, wtl, raw, ROWS, CDIM, CDIM);
    epi_split_kernel<false,false><<<nepi_c, blk>>>(raw, bk, nullptr, k_h, k_l, CDIM-1);
    transp(wv, wth, wtl, CDIM, CDIM);
    gemm_wmma_kernel<<<gc, blk, GEMM_SMEM>>>(ah, al, wth, wtl, raw, ROWS, CDIM, CDIM);
    epi_split_kernel<false,false><<<nepi_c, blk>>>(raw, bv, nullptr, v_h, v_l, CDIM-1);
    // 5. attention (128 Q-rows/CTA, cp.async KV pipeline) -> split bf16 O
    attn_mma_kernel<<<dim3(SEQ/128, BATCH*HEADS), 256, ATTN_SMEM>>>(
        q_h, q_l, k_h, k_l, v_h, v_l, o_h, o_l);
    // 6. h2 = O @ wo + bo + x (fp32, residual trunk)
    transp(wo, wth, wtl, CDIM, CDIM);
    gemm_wmma_kernel<<<gc, blk, GEMM_SMEM>>>(o_h, o_l, wth, wtl, raw, ROWS, CDIM, CDIM);
    epi_plain_kernel<true><<<nepi_c, blk>>>(raw, bo, x, h2, CDIM-1);
    // 7. LN2 -> split activation
    ln_split_kernel<<<ROWS, blk>>>(h2, ln2_w, ln2_b, ah, al);
    // 8. f1 = gelu(h3 @ fc1_w + fc1_b) -> split (reuse ah/al, FF-wide)
    transp(fc1_w, wth, wtl, CDIM, FF);
    gemm_wmma_kernel<<<gf, blk, GEMM_SMEM>>>(ah, al, wth, wtl, raw, ROWS, FF, CDIM);
    epi_split_kernel<true,false><<<nepi_f, blk>>>(raw, fc1_b, nullptr, ah, al, FF-1);
    // 9. h4 = f1 @ fc2_w + fc2_b + h2 -> split (reuse ah/al, CDIM-wide)
    transp(fc2_w, wth, wtl, FF, CDIM);
    gemm_wmma_kernel<<<gc, blk, GEMM_SMEM>>>(ah, al, wth, wtl, raw, ROWS, CDIM, FF);
    epi_split_kernel<false,true><<<nepi_c, blk>>>(raw, fc2_b, h2, ah, al, CDIM-1);
    // 10. h5 = h4 @ wout + bout (fp32, reuse h2)
    transp(wout, wth, wtl, CDIM, CDIM);
    gemm_wmma_kernel<<<gc, blk, GEMM_SMEM>>>(ah, al, wth, wtl, raw, ROWS, CDIM, CDIM);
    epi_plain_kernel<false><<<nepi_c, blk>>>(raw, bout, nullptr, h2, CDIM-1);
    // 11. out = LN(h5)
    ln_kernel<<<ROWS, blk>>>(h2, lnout_w, lnout_b, out);
}

// round 17
// speedup vs baseline: 1.0829x; 1.0829x over previous
#include <cuda_runtime.h>
#include <cuda_bf16.h>
#include <mma.h>
#include <math.h>
#include <stdint.h>

using namespace nvcuda;

// Problem constants: B=2, N=2048, C=1024, H=16, D=64
#define BATCH 2
#define SEQ   2048
#define CDIM  1024
#define HEADS 16
#define HDIM  64
#define ROWS  (BATCH*SEQ)          // 4096
#define FF    (4*CDIM)             // 4096
#define C3    (3*CDIM)             // 3072

// ---------------- scratch (static device globals) ----------------
__device__ float g_raw[(size_t)ROWS*FF];    // raw GEMM output (fp32), max 4096x4096
__device__ float g_h2 [(size_t)ROWS*CDIM];  // post-attn residual (fp32); reused for h5
__device__ __nv_bfloat16 g_ah[(size_t)ROWS*FF];    // activation hi (A operand)
__device__ __nv_bfloat16 g_al[(size_t)ROWS*FF];    // activation lo
__device__ __nv_bfloat16 g_wth[(size_t)FF*CDIM];   // transposed weight hi (fits 3xCDIM or FF rows)
__device__ __nv_bfloat16 g_wtl[(size_t)FF*CDIM];   // transposed weight lo
__device__ __nv_bfloat16 g_qh[(size_t)ROWS*CDIM], g_ql[(size_t)ROWS*CDIM];
__device__ __nv_bfloat16 g_kh[(size_t)ROWS*CDIM], g_kl[(size_t)ROWS*CDIM];
__device__ __nv_bfloat16 g_vh[(size_t)ROWS*CDIM], g_vl[(size_t)ROWS*CDIM];
__device__ __nv_bfloat16 g_oh[(size_t)ROWS*CDIM], g_ol[(size_t)ROWS*CDIM];

// ===================== helpers =====================
__device__ __forceinline__ uint32_t smem_u32(const void* p) {
    return (uint32_t)__cvta_generic_to_shared(p);
}
__device__ __forceinline__ uint32_t packbf(float lo, float hi) {
    uint32_t r;
    asm("cvt.rn.bf16x2.f32 %0, %1, %2;" : "=r"(r) : "f"(hi), "f"(lo));
    return r;
}
__device__ __forceinline__ void mma16816(float* d, const uint32_t* a, uint32_t b0, uint32_t b1) {
    asm volatile(
        "mma.sync.aligned.m16n8k16.row.col.f32.bf16.bf16.f32 "
        "{%0,%1,%2,%3}, {%4,%5,%6,%7}, {%8,%9}, {%0,%1,%2,%3};\n"
        : "+f"(d[0]), "+f"(d[1]), "+f"(d[2]), "+f"(d[3])
        : "r"(a[0]), "r"(a[1]), "r"(a[2]), "r"(a[3]), "r"(b0), "r"(b1));
}
__device__ __forceinline__ void ldsm_x2(uint32_t& r0, uint32_t& r1, uint32_t addr) {
    asm volatile("ldmatrix.sync.aligned.m8n8.x2.shared.b16 {%0,%1}, [%2];"
                 : "=r"(r0), "=r"(r1) : "r"(addr));
}
__device__ __forceinline__ void ldsm_x2_t(uint32_t& r0, uint32_t& r1, uint32_t addr) {
    asm volatile("ldmatrix.sync.aligned.m8n8.x2.trans.shared.b16 {%0,%1}, [%2];"
                 : "=r"(r0), "=r"(r1) : "r"(addr));
}
__device__ __forceinline__ void cpa16(uint32_t dst, const void* src) {
    asm volatile("cp.async.cg.shared.global [%0], [%1], 16;" :: "r"(dst), "l"(src));
}
__device__ __forceinline__ float gelu_exact(float x) {
    return x * 0.5f * (1.0f + erff(x * 0.70710678118654752f));
}
__inline__ __device__ float warp_sum(float v) {
    #pragma unroll
    for (int o = 16; o > 0; o >>= 1) v += __shfl_xor_sync(0xffffffffu, v, o);
    return v;
}

// ===================== LayerNorm (fp32 out, for final) =====================
__global__ void ln_kernel(const float* __restrict__ x, const float* __restrict__ w,
                          const float* __restrict__ b, float* __restrict__ y) {
    int row = blockIdx.x;
    int tid = threadIdx.x;
    const float4* xr = (const float4*)(x + (size_t)row * CDIM);
    float4 v = xr[tid];
    float s  = v.x + v.y + v.z + v.w;
    float ss = v.x*v.x + v.y*v.y + v.z*v.z + v.w*v.w;
    __shared__ float red_s[8], red_ss[8];
    __shared__ float s_mu, s_rstd;
    int lane = tid & 31, wid = tid >> 5;
    s = warp_sum(s); ss = warp_sum(ss);
    if (lane == 0) { red_s[wid] = s; red_ss[wid] = ss; }
    __syncthreads();
    if (tid == 0) {
        float ts = 0.f, tss = 0.f;
        #pragma unroll
        for (int i = 0; i < 8; i++) { ts += red_s[i]; tss += red_ss[i]; }
        float mu  = ts * (1.0f / CDIM);
        float var = tss * (1.0f / CDIM) - mu * mu;
        s_mu = mu; s_rstd = rsqrtf(var + 1e-5f);
    }
    __syncthreads();
    float mu = s_mu, rstd = s_rstd;
    float4 w4 = ((const float4*)w)[tid], b4 = ((const float4*)b)[tid];
    float4 o;
    o.x = (v.x - mu) * rstd * w4.x + b4.x;
    o.y = (v.y - mu) * rstd * w4.y + b4.y;
    o.z = (v.z - mu) * rstd * w4.z + b4.z;
    o.w = (v.w - mu) * rstd * w4.w + b4.w;
    ((float4*)(y + (size_t)row * CDIM))[tid] = o;
}

// ===================== LayerNorm -> split bf16 =====================
__global__ void ln_split_kernel(const float* __restrict__ x, const float* __restrict__ w,
                                const float* __restrict__ b,
                                __nv_bfloat16* __restrict__ yh, __nv_bfloat16* __restrict__ yl) {
    int row = blockIdx.x;
    int tid = threadIdx.x;
    const float4* xr = (const float4*)(x + (size_t)row * CDIM);
    float4 v = xr[tid];
    float s  = v.x + v.y + v.z + v.w;
    float ss = v.x*v.x + v.y*v.y + v.z*v.z + v.w*v.w;
    __shared__ float red_s[8], red_ss[8];
    __shared__ float s_mu, s_rstd;
    int lane = tid & 31, wid = tid >> 5;
    s = warp_sum(s); ss = warp_sum(ss);
    if (lane == 0) { red_s[wid] = s; red_ss[wid] = ss; }
    __syncthreads();
    if (tid == 0) {
        float ts = 0.f, tss = 0.f;
        #pragma unroll
        for (int i = 0; i < 8; i++) { ts += red_s[i]; tss += red_ss[i]; }
        float mu  = ts * (1.0f / CDIM);
        float var = tss * (1.0f / CDIM) - mu * mu;
        s_mu = mu; s_rstd = rsqrtf(var + 1e-5f);
    }
    __syncthreads();
    float mu = s_mu, rstd = s_rstd;
    float4 w4 = ((const float4*)w)[tid], b4 = ((const float4*)b)[tid];
    float o[4];
    o[0] = (v.x - mu) * rstd * w4.x + b4.x;
    o[1] = (v.y - mu) * rstd * w4.y + b4.y;
    o[2] = (v.z - mu) * rstd * w4.z + b4.z;
    o[3] = (v.w - mu) * rstd * w4.w + b4.w;
    size_t base = (size_t)row * CDIM + tid * 4;
    #pragma unroll
    for (int i = 0; i < 4; i += 2) {
        uint32_t hp = packbf(o[i], o[i+1]);
        __nv_bfloat162 hv = *reinterpret_cast<__nv_bfloat162*>(&hp);
        float r0 = o[i]   - __bfloat162float(hv.x);
        float r1 = o[i+1] - __bfloat162float(hv.y);
        uint32_t lp = packbf(r0, r1);
        *(uint32_t*)&yh[base + i] = hp;
        *(uint32_t*)&yl[base + i] = lp;
    }
}

// ===================== weight transpose + split: W[K,N] -> Wt[N,K] hi/lo =====================
__global__ void transpose_split_kernel(const float* __restrict__ W,
                                       __nv_bfloat16* __restrict__ Th,
                                       __nv_bfloat16* __restrict__ Tl, int K, int N) {
    __shared__ float t[32][33];
    int n0 = blockIdx.x * 32, k0 = blockIdx.y * 32;
    int tx = threadIdx.x;
    for (int i = threadIdx.y; i < 32; i += 8)
        t[i][tx] = W[(size_t)(k0 + i) * N + n0 + tx];
    __syncthreads();
    for (int i = threadIdx.y; i < 32; i += 8) {
        float x = t[tx][i];
        __nv_bfloat16 h = __float2bfloat16(x);
        __nv_bfloat16 l = __float2bfloat16(x - __bfloat162float(h));
        size_t oi = (size_t)(n0 + i) * K + k0 + tx;
        Th[oi] = h; Tl[oi] = l;
    }
}

// ===================== wmma GEMM (cp.async double-buffered, reg-diet): C = A @ Wt^T (raw fp32) =====================
#define BK    32
#define LDT   40   // padded row stride in bf16 (80B = 5x16B, 16B-aligned rows)
#define GEMM_SMEM (2*2*128*LDT*2*2)   // 2 buf x 2 hl x 128 x LDT x 2B x {A,B} = 81920

__global__ __launch_bounds__(256, 2) void gemm_wmma_kernel(
    const __nv_bfloat16* __restrict__ Ahi, const __nv_bfloat16* __restrict__ Alo,
    const __nv_bfloat16* __restrict__ Bhi, const __nv_bfloat16* __restrict__ Blo,
    float* __restrict__ C, int M, int N, int K)
{
    extern __shared__ __nv_bfloat16 dsm[];
    __nv_bfloat16* Asm = dsm;                    // [buf][hl][128][LDT]
    __nv_bfloat16* Bsm = dsm + 2*2*128*LDT;

    const int tid = threadIdx.x;
    const int wid = tid >> 5;
    const int wm = wid & 3;          // m band: rows wm*32..+31
    const int wn = wid >> 2;         // n band: cols wn*64..+63
    const size_t bm = (size_t)blockIdx.y * 128;
    const size_t bn = (size_t)blockIdx.x * 128;

    const int lr = tid >> 2;             // 0..63
    const int lc = (tid & 3) * 8;        // 0,8,16,24

    const uint32_t sA = smem_u32(Asm);
    const uint32_t sB = smem_u32(Bsm);
    const size_t s64 = (size_t)64 * K;

    auto fill = [&](int buf, int k0) {
        const __nv_bfloat16* a0 = Ahi + (bm + lr) * K + k0 + lc;
        const __nv_bfloat16* a1 = Alo + (bm + lr) * K + k0 + lc;
        const __nv_bfloat16* b0 = Bhi + (bn + lr) * K + k0 + lc;
        const __nv_bfloat16* b1 = Blo + (bn + lr) * K + k0 + lc;
        uint32_t dA0 = sA + (((buf*2+0)*128 + lr)*LDT + lc)*2;
        uint32_t dA1 = sA + (((buf*2+1)*128 + lr)*LDT + lc)*2;
        uint32_t dB0 = sB + (((buf*2+0)*128 + lr)*LDT + lc)*2;
        uint32_t dB1 = sB + (((buf*2+1)*128 + lr)*LDT + lc)*2;
        const uint32_t r64 = 64*LDT*2;
        cpa16(dA0, a0);           cpa16(dA0 + r64, a0 + s64);
        cpa16(dA1, a1);           cpa16(dA1 + r64, a1 + s64);
        cpa16(dB0, b0);           cpa16(dB0 + r64, b0 + s64);
        cpa16(dB1, b1);           cpa16(dB1 + r64, b1 + s64);
        asm volatile("cp.async.commit_group;");
    };

    wmma::fragment<wmma::accumulator, 16, 16, 16, float> acc[2][4];
    #pragma unroll
    for (int i = 0; i < 2; i++)
        #pragma unroll
        for (int j = 0; j < 4; j++)
            wmma::fill_fragment(acc[i][j], 0.0f);

    const int nch = K / BK;
    fill(0, 0);
    int buf = 0;
    for (int ch = 0; ch < nch; ch++) {
        if (ch + 1 < nch) {
            fill(buf ^ 1, (ch + 1) * BK);
            asm volatile("cp.async.wait_group 1;");
        } else {
            asm volatile("cp.async.wait_group 0;");
        }
        __syncthreads();

        const __nv_bfloat16* Ah = Asm + (buf*2+0)*128*LDT;
        const __nv_bfloat16* Al = Asm + (buf*2+1)*128*LDT;
        const __nv_bfloat16* Bh = Bsm + (buf*2+0)*128*LDT;
        const __nv_bfloat16* Bl = Bsm + (buf*2+1)*128*LDT;

        #pragma unroll
        for (int kk = 0; kk < BK; kk += 16) {
            wmma::fragment<wmma::matrix_a, 16, 16, 16, __nv_bfloat16, wmma::row_major> aH[2], aL[2];
            #pragma unroll
            for (int i = 0; i < 2; i++) {
                wmma::load_matrix_sync(aH[i], Ah + (wm*32 + i*16)*LDT + kk, LDT);
                wmma::load_matrix_sync(aL[i], Al + (wm*32 + i*16)*LDT + kk, LDT);
            }
            #pragma unroll
            for (int jh = 0; jh < 2; jh++) {
                wmma::fragment<wmma::matrix_b, 16, 16, 16, __nv_bfloat16, wmma::col_major> bH[2], bL[2];
                #pragma unroll
                for (int j = 0; j < 2; j++) {
                    int ncol = wn*64 + jh*32 + j*16;
                    wmma::load_matrix_sync(bH[j], Bh + ncol*LDT + kk, LDT);
                    wmma::load_matrix_sync(bL[j], Bl + ncol*LDT + kk, LDT);
                }
                #pragma unroll
                for (int i = 0; i < 2; i++)
                    #pragma unroll
                    for (int j = 0; j < 2; j++) {
                        wmma::mma_sync(acc[i][jh*2+j], aH[i], bH[j], acc[i][jh*2+j]);
                        wmma::mma_sync(acc[i][jh*2+j], aH[i], bL[j], acc[i][jh*2+j]);
                        wmma::mma_sync(acc[i][jh*2+j], aL[i], bH[j], acc[i][jh*2+j]);
                    }
            }
        }
        __syncthreads();
        buf ^= 1;
    }

    #pragma unroll
    for (int i = 0; i < 2; i++)
        #pragma unroll
        for (int j = 0; j < 4; j++) {
            float* dst = C + (bm + wm*32 + i*16) * N + bn + wn*64 + j*16;
            wmma::store_matrix_sync(dst, acc[i][j], N, wmma::mem_row_major);
        }
}

// ===================== epilogues =====================
template<bool GELU, bool RES>
__global__ void epi_split_kernel(const float* __restrict__ Craw, const float* __restrict__ bias,
                                 const float* __restrict__ res,
                                 __nv_bfloat16* __restrict__ oh, __nv_bfloat16* __restrict__ ol,
                                 int nmask) {
    int i = (blockIdx.x * blockDim.x + threadIdx.x) * 4;
    int col = i & nmask;
    float4 v = *(const float4*)(Craw + i);
    float4 b = *(const float4*)(bias + col);
    float o[4] = {v.x + b.x, v.y + b.y, v.z + b.z, v.w + b.w};
    if (RES) {
        float4 r = *(const float4*)(res + i);
        o[0] += r.x; o[1] += r.y; o[2] += r.z; o[3] += r.w;
    }
    if (GELU) {
        #pragma unroll
        for (int j = 0; j < 4; j++) o[j] = gelu_exact(o[j]);
    }
    #pragma unroll
    for (int j = 0; j < 4; j += 2) {
        uint32_t hp = packbf(o[j], o[j+1]);
        __nv_bfloat162 hv = *reinterpret_cast<__nv_bfloat162*>(&hp);
        float r0 = o[j]   - __bfloat162float(hv.x);
        float r1 = o[j+1] - __bfloat162float(hv.y);
        uint32_t lp = packbf(r0, r1);
        *(uint32_t*)&oh[i + j] = hp;
        *(uint32_t*)&ol[i + j] = lp;
    }
}

// epilogue for packed QKV raw [ROWS, 3072]: per-third bias + split into q/k/v buffers
__global__ void epi_split3_kernel(const float* __restrict__ Craw,
                                  const float* __restrict__ bq, const float* __restrict__ bk,
                                  const float* __restrict__ bv,
                                  __nv_bfloat16* __restrict__ q_h, __nv_bfloat16* __restrict__ q_l,
                                  __nv_bfloat16* __restrict__ k_h, __nv_bfloat16* __restrict__ k_l,
                                  __nv_bfloat16* __restrict__ v_h, __nv_bfloat16* __restrict__ v_l) {
    int i = (blockIdx.x * blockDim.x + threadIdx.x) * 4;     // over ROWS*C3
    int row = i / C3;
    int col = i - row * C3;          // 0..3071, 4-aligned, stays within one third
    int third = col >> 10;           // 0,1,2
    int c = col & (CDIM - 1);
    const float* bias = (third == 0) ? bq : (third == 1) ? bk : bv;
    __nv_bfloat16* oh = (third == 0) ? q_h : (third == 1) ? k_h : v_h;
    __nv_bfloat16* ol = (third == 0) ? q_l : (third == 1) ? k_l : v_l;
    float4 v = *(const float4*)(Craw + i);
    float4 b = *(const float4*)(bias + c);
    float o[4] = {v.x + b.x, v.y + b.y, v.z + b.z, v.w + b.w};
    size_t dst = (size_t)row * CDIM + c;
    #pragma unroll
    for (int j = 0; j < 4; j += 2) {
        uint32_t hp = packbf(o[j], o[j+1]);
        __nv_bfloat162 hv = *reinterpret_cast<__nv_bfloat162*>(&hp);
        float r0 = o[j]   - __bfloat162float(hv.x);
        float r1 = o[j+1] - __bfloat162float(hv.y);
        uint32_t lp = packbf(r0, r1);
        *(uint32_t*)&oh[dst + j] = hp;
        *(uint32_t*)&ol[dst + j] = lp;
    }
}

template<bool RES>
__global__ void epi_plain_kernel(const float* __restrict__ Craw, const float* __restrict__ bias,
                                 const float* __restrict__ res, float* __restrict__ out,
                                 int nmask) {
    int i = (blockIdx.x * blockDim.x + threadIdx.x) * 4;
    int col = i & nmask;
    float4 v = *(const float4*)(Craw + i);
    float4 b = *(const float4*)(bias + col);
    v.x += b.x; v.y += b.y; v.z += b.z; v.w += b.w;
    if (RES) {
        float4 r = *(const float4*)(res + i);
        v.x += r.x; v.y += r.y; v.z += r.z; v.w += r.w;
    }
    *(float4*)(out + i) = v;
}

// ===================== tensor-core flash attention (64 Q-rows/CTA, cp.async KV pipeline) =====================
// R15-proven config: 128 threads (4 warps), 3 CTAs/SM co-residency.
#define AP 72
#define ATTN_PLANE_B (64*AP*2)             // 9216 bytes per plane
#define ATTN_STAGE_B (4*ATTN_PLANE_B)      // 36864 (Kh, Kl, Vh, Vl)
#define ATTN_SMEM    (2*ATTN_STAGE_B)      // 73728, dynamic (opt-in)

__global__ __launch_bounds__(128) void attn_mma_kernel(
    const __nv_bfloat16* __restrict__ qh, const __nv_bfloat16* __restrict__ ql,
    const __nv_bfloat16* __restrict__ kh, const __nv_bfloat16* __restrict__ kl,
    const __nv_bfloat16* __restrict__ vh, const __nv_bfloat16* __restrict__ vl,
    __nv_bfloat16* __restrict__ oh, __nv_bfloat16* __restrict__ ol)
{
    extern __shared__ char asmem[];
    const uint32_t sbase = smem_u32(asmem);

    const int tid = threadIdx.x, wid = tid >> 5, lane = tid & 31;
    const int g = lane >> 2, tig = lane & 3;
    const int bh = blockIdx.y, b = bh / HEADS, h = bh % HEADS;
    const int q0 = blockIdx.x * 64;
    const int hcol = h * HDIM;
    const size_t qrow = (size_t)b * SEQ + q0 + wid * 16;

    uint32_t aQh[4][4], aQl[4][4];
    {
        const size_t r0 = (qrow + g) * CDIM, r1 = (qrow + g + 8) * CDIM;
        #pragma unroll
        for (int kk = 0; kk < 4; kk++) {
            int c0 = hcol + kk * 16 + 2 * tig, c1 = c0 + 8;
            aQh[kk][0] = *(const uint32_t*)&qh[r0 + c0];
            aQh[kk][1] = *(const uint32_t*)&qh[r1 + c0];
            aQh[kk][2] = *(const uint32_t*)&qh[r0 + c1];
            aQh[kk][3] = *(const uint32_t*)&qh[r1 + c1];
            aQl[kk][0] = *(const uint32_t*)&ql[r0 + c0];
            aQl[kk][1] = *(const uint32_t*)&ql[r1 + c0];
            aQl[kk][2] = *(const uint32_t*)&ql[r0 + c1];
            aQl[kk][3] = *(const uint32_t*)&ql[r1 + c1];
        }
    }

    auto fillkv = [&](int st, int kv0) {
        uint32_t base = sbase + st * ATTN_STAGE_B;
        #pragma unroll
        for (int i = 0; i < 4; i++) {
            int idx = tid + i * 128;
            int r = idx >> 3, c8 = (idx & 7) * 8;
            size_t gsrc = ((size_t)b * SEQ + kv0 + r) * CDIM + hcol + c8;
            uint32_t doff = (uint32_t)((r * AP + c8) * 2);
            cpa16(base + 0*ATTN_PLANE_B + doff, &kh[gsrc]);
            cpa16(base + 1*ATTN_PLANE_B + doff, &kl[gsrc]);
            cpa16(base + 2*ATTN_PLANE_B + doff, &vh[gsrc]);
            cpa16(base + 3*ATTN_PLANE_B + doff, &vl[gsrc]);
        }
        asm volatile("cp.async.commit_group;");
    };

    const int rsub  = lane & 7;
    const int chalf = ((lane >> 3) & 1) * 8;
    const int rv    = lane & 15;

    float of[8][4];
    #pragma unroll
    for (int j = 0; j < 8; j++) { of[j][0]=0.f; of[j][1]=0.f; of[j][2]=0.f; of[j][3]=0.f; }
    float m0 = -1e30f, m1 = -1e30f, l0 = 0.f, l1 = 0.f;

    fillkv(0, 0);
    int buf = 0;
    for (int kv0 = 0; kv0 < SEQ; kv0 += 64) {
        if (kv0 + 64 < SEQ) {
            fillkv(buf ^ 1, kv0 + 64);
            asm volatile("cp.async.wait_group 1;");
        } else {
            asm volatile("cp.async.wait_group 0;");
        }
        __syncthreads();

        const uint32_t kshb = sbase + buf*ATTN_STAGE_B + 0*ATTN_PLANE_B;
        const uint32_t kslb = sbase + buf*ATTN_STAGE_B + 1*ATTN_PLANE_B;
        const uint32_t vshb = sbase + buf*ATTN_STAGE_B + 2*ATTN_PLANE_B;
        const uint32_t vslb = sbase + buf*ATTN_STAGE_B + 3*ATTN_PLANE_B;

        float s[8][4];
        #pragma unroll
        for (int nt = 0; nt < 8; nt++) { s[nt][0]=0.f; s[nt][1]=0.f; s[nt][2]=0.f; s[nt][3]=0.f; }
        #pragma unroll
        for (int kk = 0; kk < 4; kk++) {
            #pragma unroll
            for (int nt = 0; nt < 8; nt++) {
                uint32_t off = (uint32_t)(((nt*8 + rsub)*AP + kk*16 + chalf) * 2);
                uint32_t bh0, bh1, bl0, bl1;
                ldsm_x2(bh0, bh1, kshb + off);
                ldsm_x2(bl0, bl1, kslb + off);
                mma16816(s[nt], aQh[kk], bh0, bh1);
                mma16816(s[nt], aQh[kk], bl0, bl1);
                mma16816(s[nt], aQl[kk], bh0, bh1);
            }
        }

        float mx0 = -1e30f, mx1 = -1e30f;
        #pragma unroll
        for (int nt = 0; nt < 8; nt++) {
            s[nt][0] *= 0.125f; s[nt][1] *= 0.125f; s[nt][2] *= 0.125f; s[nt][3] *= 0.125f;
            mx0 = fmaxf(mx0, fmaxf(s[nt][0], s[nt][1]));
            mx1 = fmaxf(mx1, fmaxf(s[nt][2], s[nt][3]));
        }
        mx0 = fmaxf(mx0, __shfl_xor_sync(0xffffffffu, mx0, 1));
        mx0 = fmaxf(mx0, __shfl_xor_sync(0xffffffffu, mx0, 2));
        mx1 = fmaxf(mx1, __shfl_xor_sync(0xffffffffu, mx1, 1));
        mx1 = fmaxf(mx1, __shfl_xor_sync(0xffffffffu, mx1, 2));
        float m0n = fmaxf(m0, mx0), m1n = fmaxf(m1, mx1);
        float f0 = __expf(m0 - m0n), f1 = __expf(m1 - m1n);
        m0 = m0n; m1 = m1n;

        float ps0 = 0.f, ps1 = 0.f;
        #pragma unroll
        for (int nt = 0; nt < 8; nt++) {
            s[nt][0] = __expf(s[nt][0] - m0); ps0 += s[nt][0];
            s[nt][1] = __expf(s[nt][1] - m0); ps0 += s[nt][1];
            s[nt][2] = __expf(s[nt][2] - m1); ps1 += s[nt][2];
            s[nt][3] = __expf(s[nt][3] - m1); ps1 += s[nt][3];
        }
        ps0 += __shfl_xor_sync(0xffffffffu, ps0, 1);
        ps0 += __shfl_xor_sync(0xffffffffu, ps0, 2);
        ps1 += __shfl_xor_sync(0xffffffffu, ps1, 1);
        ps1 += __shfl_xor_sync(0xffffffffu, ps1, 2);
        l0 = l0 * f0 + ps0;
        l1 = l1 * f1 + ps1;

        #pragma unroll
        for (int j = 0; j < 8; j++) {
            of[j][0] *= f0; of[j][1] *= f0; of[j][2] *= f1; of[j][3] *= f1;
        }

        uint32_t pha[8], phb[8], pla[8], plb[8];
        #pragma unroll
        for (int nt = 0; nt < 8; nt++) {
            uint32_t hp = packbf(s[nt][0], s[nt][1]);
            __nv_bfloat162 hv = *reinterpret_cast<__nv_bfloat162*>(&hp);
            pla[nt] = packbf(s[nt][0] - __bfloat162float(hv.x),
                             s[nt][1] - __bfloat162float(hv.y));
            pha[nt] = hp;
            uint32_t hp2 = packbf(s[nt][2], s[nt][3]);
            __nv_bfloat162 hv2 = *reinterpret_cast<__nv_bfloat162*>(&hp2);
            plb[nt] = packbf(s[nt][2] - __bfloat162float(hv2.x),
                             s[nt][3] - __bfloat162float(hv2.y));
            phb[nt] = hp2;
        }

        #pragma unroll
        for (int kk = 0; kk < 4; kk++) {
            uint32_t aH[4] = {pha[2*kk], phb[2*kk], pha[2*kk+1], phb[2*kk+1]};
            uint32_t aL[4] = {pla[2*kk], plb[2*kk], pla[2*kk+1], plb[2*kk+1]};
            #pragma unroll
            for (int j = 0; j < 8; j++) {
                uint32_t off = (uint32_t)(((kk*16 + rv)*AP + j*8) * 2);
                uint32_t bh0, bh1, bl0, bl1;
                ldsm_x2_t(bh0, bh1, vshb + off);
                ldsm_x2_t(bl0, bl1, vslb + off);
                mma16816(of[j], aH, bh0, bh1);
                mma16816(of[j], aH, bl0, bl1);
                mma16816(of[j], aL, bh0, bh1);
            }
        }
        __syncthreads();
        buf ^= 1;
    }

    float inv0 = 1.0f / l0, inv1 = 1.0f / l1;
    const size_t r0 = (qrow + g) * CDIM, r1 = (qrow + g + 8) * CDIM;
    #pragma unroll
    for (int j = 0; j < 8; j++) {
        int col = hcol + j * 8 + 2 * tig;
        float v0 = of[j][0] * inv0, v1 = of[j][1] * inv0;
        float v2 = of[j][2] * inv1, v3 = of[j][3] * inv1;
        uint32_t hp0 = packbf(v0, v1);
        __nv_bfloat162 h0 = *reinterpret_cast<__nv_bfloat162*>(&hp0);
        uint32_t lp0 = packbf(v0 - __bfloat162float(h0.x), v1 - __bfloat162float(h0.y));
        uint32_t hp1 = packbf(v2, v3);
        __nv_bfloat162 h1 = *reinterpret_cast<__nv_bfloat162*>(&hp1);
        uint32_t lp1 = packbf(v2 - __bfloat162float(h1.x), v3 - __bfloat162float(h1.y));
        *(uint32_t*)&oh[r0 + col] = hp0;
        *(uint32_t*)&ol[r0 + col] = lp0;
        *(uint32_t*)&oh[r1 + col] = hp1;
        *(uint32_t*)&ol[r1 + col] = lp1;
    }
}

// ===================== host =====================
static inline void transp(const float* W, __nv_bfloat16* th, __nv_bfloat16* tl, int K, int N) {
    transpose_split_kernel<<<dim3(N / 32, K / 32), dim3(32, 8)>>>(W, th, tl, K, N);
}

extern "C" void kernel_launch(void* const* d_in, const int* in_sizes, int n_in,
                              void* d_out, int out_size)
{
    const float* x      = (const float*)d_in[0];
    const float* wq     = (const float*)d_in[1];
    const float* bq     = (const float*)d_in[2];
    const float* wk     = (const float*)d_in[3];
    const float* bk     = (const float*)d_in[4];
    const float* wv     = (const float*)d_in[5];
    const float* bv     = (const float*)d_in[6];
    const float* wo     = (const float*)d_in[7];
    const float* bo     = (const float*)d_in[8];
    const float* ln1_w  = (const float*)d_in[9];
    const float* ln1_b  = (const float*)d_in[10];
    const float* ln2_w  = (const float*)d_in[11];
    const float* ln2_b  = (const float*)d_in[12];
    const float* fc1_w  = (const float*)d_in[13];
    const float* fc1_b  = (const float*)d_in[14];
    const float* fc2_w  = (const float*)d_in[15];
    const float* fc2_b  = (const float*)d_in[16];
    const float* wout   = (const float*)d_in[17];
    const float* bout   = (const float*)d_in[18];
    const float* lnout_w= (const float*)d_in[19];
    const float* lnout_b= (const float*)d_in[20];
    float* out = (float*)d_out;

    float *raw, *h2;
    __nv_bfloat16 *ah, *al, *wth, *wtl, *q_h, *q_l, *k_h, *k_l, *v_h, *v_l, *o_h, *o_l;
    cudaGetSymbolAddress((void**)&raw, g_raw);
    cudaGetSymbolAddress((void**)&h2,  g_h2);
    cudaGetSymbolAddress((void**)&ah,  g_ah);
    cudaGetSymbolAddress((void**)&al,  g_al);
    cudaGetSymbolAddress((void**)&wth, g_wth);
    cudaGetSymbolAddress((void**)&wtl, g_wtl);
    cudaGetSymbolAddress((void**)&q_h, g_qh);  cudaGetSymbolAddress((void**)&q_l, g_ql);
    cudaGetSymbolAddress((void**)&k_h, g_kh);  cudaGetSymbolAddress((void**)&k_l, g_kl);
    cudaGetSymbolAddress((void**)&v_h, g_vh);  cudaGetSymbolAddress((void**)&v_l, g_vl);
    cudaGetSymbolAddress((void**)&o_h, g_oh);  cudaGetSymbolAddress((void**)&o_l, g_ol);

    cudaFuncSetAttribute(gemm_wmma_kernel,
                         cudaFuncAttributeMaxDynamicSharedMemorySize, GEMM_SMEM);
    cudaFuncSetAttribute(attn_mma_kernel,
                         cudaFuncAttributeMaxDynamicSharedMemorySize, ATTN_SMEM);

    dim3 blk(256);
    dim3 gq(C3/128,   ROWS/128);   // (24, 32) fused QKV
    dim3 gc(CDIM/128, ROWS/128);   // (8, 32)
    dim3 gf(FF/128,   ROWS/128);   // (32, 32)
    const int nepi_c = ROWS*CDIM/1024;
    const int nepi_q = ROWS*C3/1024;
    const int nepi_f = ROWS*FF/1024;

    // 1. LN1 -> split activation
    ln_split_kernel<<<ROWS, blk>>>(x, ln1_w, ln1_b, ah, al);
    // 2. fused QKV projection (N=3072, packed transposed weights) -> split q,k,v
    transp(wq, wth,                       wtl,                       CDIM, CDIM);
    transp(wk, wth + (size_t)CDIM*CDIM,   wtl + (size_t)CDIM*CDIM,   CDIM, CDIM);
    transp(wv, wth + (size_t)2*CDIM*CDIM, wtl + (size_t)2*CDIM*CDIM, CDIM, CDIM);
    gemm_wmma_kernel<<<gq, blk, GEMM_SMEM>>>(ah, al, wth, wtl, raw, ROWS, C3, CDIM);
    epi_split3_kernel<<<nepi_q, blk>>>(raw, bq, bk, bv, q_h, q_l, k_h, k_l, v_h, v_l);
    // 3. attention (64 Q-rows/CTA, cp.async KV pipeline) -> split bf16 O
    attn_mma_kernel<<<dim3(SEQ/64, BATCH*HEADS), 128, ATTN_SMEM>>>(
        q_h, q_l, k_h, k_l, v_h, v_l, o_h, o_l);
    // 4. h2 = O @ wo + bo + x (fp32, residual trunk)
    transp(wo, wth, wtl, CDIM, CDIM);
    gemm_wmma_kernel<<<gc, blk, GEMM_SMEM>>>(o_h, o_l, wth, wtl, raw, ROWS, CDIM, CDIM);
    epi_plain_kernel<true><<<nepi_c, blk>>>(raw, bo, x, h2, CDIM-1);
    // 5. LN2 -> split activation
    ln_split_kernel<<<ROWS, blk>>>(h2, ln2_w, ln2_b, ah, al);
    // 6. f1 = gelu(h3 @ fc1_w + fc1_b) -> split (reuse ah/al, FF-wide)
    transp(fc1_w, wth, wtl, CDIM, FF);
    gemm_wmma_kernel<<<gf, blk, GEMM_SMEM>>>(ah, al, wth, wtl, raw, ROWS, FF, CDIM);
    epi_split_kernel<true,false><<<nepi_f, blk>>>(raw, fc1_b, nullptr, ah, al, FF-1);
    // 7. h4 = f1 @ fc2_w + fc2_b + h2 -> split (reuse ah/al, CDIM-wide)
    transp(fc2_w, wth, wtl, FF, CDIM);
    gemm_wmma_kernel<<<gc, blk, GEMM_SMEM>>>(ah, al, wth, wtl, raw, ROWS, CDIM, FF);
    epi_split_kernel<false,true><<<nepi_c, blk>>>(raw, fc2_b, h2, ah, al, CDIM-1);
    // 8. h5 = h4 @ wout + bout (fp32, reuse h2)
    transp(wout, wth, wtl, CDIM, CDIM);
    gemm_wmma_kernel<<<gc, blk, GEMM_SMEM>>>(ah, al, wth, wtl, raw, ROWS, CDIM, CDIM);
    epi_plain_kernel<false><<<nepi_c, blk>>>(raw, bout, nullptr, h2, CDIM-1);
    // 9. out = LN(h5)
    ln_kernel<<<ROWS, blk>>>(h2, lnout_w, lnout_b, out);
}